// round 10
// baseline (speedup 1.0000x reference)
#include <cuda_runtime.h>
#include <math.h>
#include <stdint.h>

#define N_NODES 2048
#define IN_F    128
#define OUT_F   32
#define KC      128
#define NTILES  (N_NODES / KC)          // 16
#define NSTEP   (KC / 32)               // 4
#define THREADS 96                      // 3 warps: rows {0,1},{2,3},{4,4dup}
#define ROWS_CTA 5
#define GRID    410                     // ceil(2048/5)
#define LOG2E 1.4426950408889634f

// Stage layout: [0,8K) fp16 score tile | [8K,24K) fp32 agg tile | [24K,+512) dk
#define SC_BYTES   (KC * OUT_F * 2)          // 8192
#define AG_BYTES   (KC * OUT_F * 4)          // 16384
#define DK_OFF     (SC_BYTES + AG_BYTES)     // 24576
#define STAGE_BYTES (DK_OFF + KC * 4)        // 25088
#define SMEM_BYTES (2 * STAGE_BYTES)         // 50176

__device__ float          g_Wh1[N_NODES * OUT_F];   // fp32 Wh1 (agg tile)
__device__ unsigned short g_Wh2h[N_NODES * OUT_F];  // fp16 Wh2 (score tile)
__device__ float          g_c6L[N_NODES];           // log2e*0.6*dot(a,Wh1[i])
__device__ float          g_dk6L[N_NODES];          // log2e*0.6*dot(a,Wh2[k])

// ---------------------------------------------------------------------------
// Kernel 1: projections + constants (+ fp16 copy of Wh2). 512 CTAs x 128 thr.
// ---------------------------------------------------------------------------
__global__ __launch_bounds__(128) void gat_gemm_kernel(
    const float* __restrict__ h, const float* __restrict__ W,
    const float* __restrict__ a)
{
    __shared__ float Ws[2 * IN_F * OUT_F];
    __shared__ float hs[4][IN_F];
    const int tid = threadIdx.x, w = tid >> 5, lane = tid & 31;
    const int row0 = blockIdx.x * 4;
    {
        const uint32_t wsb = (uint32_t)__cvta_generic_to_shared(Ws);
        const uint32_t hsb = (uint32_t)__cvta_generic_to_shared(&hs[0][0]);
        const float4* gw = (const float4*)W;
        const float4* gh = (const float4*)(h + (size_t)row0 * IN_F);
#pragma unroll
        for (int i = 0; i < 16; ++i)
            asm volatile("cp.async.cg.shared.global [%0], [%1], 16;"
                         :: "r"(wsb + (uint32_t)((tid + i * 128) * 16)),
                            "l"(gw + tid + i * 128) : "memory");
        asm volatile("cp.async.cg.shared.global [%0], [%1], 16;"
                     :: "r"(hsb + (uint32_t)(tid * 16)), "l"(gh + tid) : "memory");
        asm volatile("cp.async.commit_group;" ::: "memory");
        asm volatile("cp.async.wait_group 0;" ::: "memory");
    }
    __syncthreads();

    const int row = row0 + w;
    float wh1 = 0.f, wh2 = 0.f;
#pragma unroll 8
    for (int j = 0; j < IN_F; ++j) {
        const float hv = hs[w][j];
        wh1 = fmaf(hv, Ws[j * OUT_F + lane], wh1);
        wh2 = fmaf(hv, Ws[(IN_F + j) * OUT_F + lane], wh2);
    }
    g_Wh1[row * OUT_F + lane] = wh1;
    unsigned short h2;
    asm("cvt.rn.f16.f32 %0, %1;" : "=h"(h2) : "f"(wh2));
    g_Wh2h[row * OUT_F + lane] = h2;

    const float av = __ldg(a + lane);
    float c = av * wh1, d = av * wh2;
#pragma unroll
    for (int o = 16; o; o >>= 1) {
        c += __shfl_xor_sync(0xffffffffu, c, o);
        d += __shfl_xor_sync(0xffffffffu, d, o);
    }
    if (lane == 0) {
        g_c6L[row]  = (0.6f * LOG2E) * c;
        g_dk6L[row] = (0.6f * LOG2E) * d;
    }
}

// ---------------------------------------------------------------------------
// Kernel 2: fused score(fp16) + softmax + agg(fp32) + ELU. 96 thr, occ 3.
// ---------------------------------------------------------------------------
extern __shared__ float smem2[];

__device__ __forceinline__ void issue_tile(int t, uint32_t smem_u, int tid)
{
    const uint32_t sb = smem_u + (t & 1) * STAGE_BYTES;
    // fp16 score tile: 512 chunks of 16B, swizzle q^((kk>>1)&3)
    const float4* g2 = (const float4*)(g_Wh2h + (size_t)t * (KC * OUT_F));
    for (int i = tid; i < KC * 4; i += THREADS) {
        int kk = i >> 2, q = i & 3;
        uint32_t soff = (uint32_t)(kk * 64 + ((q ^ ((kk >> 1) & 3)) << 4));
        asm volatile("cp.async.cg.shared.global [%0], [%1], 16;"
                     :: "r"(sb + soff), "l"(g2 + i) : "memory");
    }
    // fp32 agg tile: 1024 chunks, swizzle f4^(kk&7)
    const float4* g1 = ((const float4*)g_Wh1) + t * (KC * 8);
    for (int i = tid; i < KC * 8; i += THREADS) {
        int kk = i >> 3, f4 = i & 7;
        uint32_t soff = (uint32_t)(((kk << 3) | (f4 ^ (kk & 7))) << 4);
        asm volatile("cp.async.cg.shared.global [%0], [%1], 16;"
                     :: "r"(sb + SC_BYTES + soff), "l"(g1 + i) : "memory");
    }
    const float* gd = g_dk6L + t * KC;
    for (int i = tid; i < KC; i += THREADS)
        asm volatile("cp.async.ca.shared.global [%0], [%1], 4;"
                     :: "r"(sb + DK_OFF + (uint32_t)(i * 4)), "l"(gd + i) : "memory");
    asm volatile("cp.async.commit_group;" ::: "memory");
}

__global__ __launch_bounds__(THREADS, 3) void gat_attn_kernel(
    const int* __restrict__ adj, const float* __restrict__ a,
    float* __restrict__ out)
{
    const int tid = threadIdx.x, w = tid >> 5, lane = tid & 31;
    const uint32_t smem_u = (uint32_t)__cvta_generic_to_shared(smem2);
    const int base = blockIdx.x * ROWS_CTA;
    int row0 = base + (2 * w < 4 ? 2 * w : 4);
    int row1 = base + (2 * w + 1 < 4 ? 2 * w + 1 : 4);
    if (row0 > N_NODES - 1) row0 = N_NODES - 1;
    if (row1 > N_NODES - 1) row1 = N_NODES - 1;

    // fp16x2 score operands; fp32x2 accumulators
    uint32_t wh1pH[2][16], a4LH[16];
    unsigned long long acc[2][16];
#pragma unroll
    for (int j = 0; j < 16; ++j) {
        float a0 = __ldg(a + 2 * j), a1 = __ldg(a + 2 * j + 1);
        float A0 = (0.4f * LOG2E) * a0, A1 = (0.4f * LOG2E) * a1;
        float x0 = g_Wh1[row0 * OUT_F + 2 * j], x1 = g_Wh1[row0 * OUT_F + 2 * j + 1];
        float y0 = g_Wh1[row1 * OUT_F + 2 * j], y1 = g_Wh1[row1 * OUT_F + 2 * j + 1];
        asm("{.reg .f16 l, hh; cvt.rn.f16.f32 l, %1; cvt.rn.f16.f32 hh, %2; mov.b32 %0, {l, hh};}"
            : "=r"(a4LH[j]) : "f"(A0), "f"(A1));
        asm("{.reg .f16 l, hh; cvt.rn.f16.f32 l, %1; cvt.rn.f16.f32 hh, %2; mov.b32 %0, {l, hh};}"
            : "=r"(wh1pH[0][j]) : "f"(x0), "f"(x1));
        asm("{.reg .f16 l, hh; cvt.rn.f16.f32 l, %1; cvt.rn.f16.f32 hh, %2; mov.b32 %0, {l, hh};}"
            : "=r"(wh1pH[1][j]) : "f"(y0), "f"(y1));
        acc[0][j] = 0ull; acc[1][j] = 0ull;
    }
    const float c0 = g_c6L[row0], c1 = g_c6L[row1];
    float lsum0 = 0.f, lsum1 = 0.f;

    const int* adjr0 = adj + (size_t)row0 * N_NODES;
    const int* adjr1 = adj + (size_t)row1 * N_NODES;
    int am0[NSTEP], am1[NSTEP];
#pragma unroll
    for (int s = 0; s < NSTEP; ++s) {
        am0[s] = __ldg(adjr0 + (s << 5) + lane);
        am1[s] = __ldg(adjr1 + (s << 5) + lane);
    }

    issue_tile(0, smem_u, tid);

#pragma unroll 1
    for (int t = 0; t < NTILES; ++t) {
        __syncthreads();
        if (t + 1 < NTILES) {
            issue_tile(t + 1, smem_u, tid);
            asm volatile("cp.async.wait_group 1;" ::: "memory");
        } else {
            asm volatile("cp.async.wait_group 0;" ::: "memory");
        }
        __syncthreads();

        const uint32_t sb = smem_u + (t & 1) * STAGE_BYTES;
        const float* sdk = (const float*)((const char*)smem2 + (t & 1) * STAGE_BYTES + DK_OFF);
        const int tn = (t + 1) & (NTILES - 1);
        const int* nadj0 = adjr0 + (tn << 7);
        const int* nadj1 = adjr1 + (tn << 7);

#pragma unroll
        for (int step = 0; step < NSTEP; ++step) {
            const int kk = (step << 5) | lane;
            const int av0 = am0[step], av1 = am1[step];
            am0[step] = __ldg(nadj0 + (step << 5) + lane);
            am1[step] = __ldg(nadj1 + (step << 5) + lane);
            const float dkv = sdk[kk];

            // ---- Score (fp16x2): 4 swizzled LDS.128 -> 16 fp16x2 ----
            uint32_t hh[16];
            {
                const uint32_t rb = sb + (uint32_t)(kk * 64);
                const int sw = (kk >> 1) & 3;
#pragma unroll
                for (int q = 0; q < 4; ++q)
                    asm volatile("ld.shared.v4.b32 {%0, %1, %2, %3}, [%4];"
                                 : "=r"(hh[4*q]), "=r"(hh[4*q+1]), "=r"(hh[4*q+2]), "=r"(hh[4*q+3])
                                 : "r"(rb + (uint32_t)((q ^ sw) << 4)));
            }
            uint32_t s0[4] = {0,0,0,0}, s1[4] = {0,0,0,0};
#pragma unroll
            for (int j = 0; j < 16; ++j) {
                uint32_t t0, t1;
                asm("add.rn.f16x2 %0, %1, %2;" : "=r"(t0) : "r"(wh1pH[0][j]), "r"(hh[j]));
                t0 &= 0x7fff7fffu;
                asm("fma.rn.f16x2 %0, %1, %2, %0;" : "+r"(s0[j & 3]) : "r"(a4LH[j]), "r"(t0));
                asm("add.rn.f16x2 %0, %1, %2;" : "=r"(t1) : "r"(wh1pH[1][j]), "r"(hh[j]));
                t1 &= 0x7fff7fffu;
                asm("fma.rn.f16x2 %0, %1, %2, %0;" : "+r"(s1[j & 3]) : "r"(a4LH[j]), "r"(t1));
            }
            float p0, p1;
            {
                uint32_t u; float lo, hi, e;
                asm("add.rn.f16x2 %0, %1, %2;" : "=r"(u) : "r"(s0[0]), "r"(s0[1]));
                asm("add.rn.f16x2 %0, %1, %2;" : "=r"(s0[2]) : "r"(s0[2]), "r"(s0[3]));
                asm("add.rn.f16x2 %0, %1, %2;" : "=r"(u) : "r"(u), "r"(s0[2]));
                asm("{.reg .f16 l, hh; mov.b32 {l, hh}, %2; cvt.f32.f16 %0, l; cvt.f32.f16 %1, hh;}"
                    : "=f"(lo), "=f"(hi) : "r"(u));
                e = (c0 + dkv) + (lo + hi);
                asm("ex2.approx.f32 %0, %1;" : "=f"(p0) : "f"(e));
                p0 = (av0 > 0) ? p0 : 0.f;
                asm("add.rn.f16x2 %0, %1, %2;" : "=r"(u) : "r"(s1[0]), "r"(s1[1]));
                asm("add.rn.f16x2 %0, %1, %2;" : "=r"(s1[2]) : "r"(s1[2]), "r"(s1[3]));
                asm("add.rn.f16x2 %0, %1, %2;" : "=r"(u) : "r"(u), "r"(s1[2]));
                asm("{.reg .f16 l, hh; mov.b32 {l, hh}, %2; cvt.f32.f16 %0, l; cvt.f32.f16 %1, hh;}"
                    : "=f"(lo), "=f"(hi) : "r"(u));
                e = (c1 + dkv) + (lo + hi);
                asm("ex2.approx.f32 %0, %1;" : "=f"(p1) : "f"(e));
                p1 = (av1 > 0) ? p1 : 0.f;
            }
            lsum0 += p0; lsum1 += p1;
            unsigned long long p20, p21;
            asm("mov.b64 %0, {%1, %1};" : "=l"(p20) : "f"(p0));
            asm("mov.b64 %0, {%1, %1};" : "=l"(p21) : "f"(p1));

            // ---- Aggregate (fp32x2) ----
            const uint32_t rb1 = sb + SC_BYTES + (uint32_t)(kk << 7);
            const int sx = kk & 7;
#pragma unroll
            for (int f4 = 0; f4 < 8; ++f4) {
                unsigned long long v0, v1;
                asm volatile("ld.shared.v2.b64 {%0, %1}, [%2];"
                             : "=l"(v0), "=l"(v1) : "r"(rb1 + (uint32_t)((f4 ^ sx) << 4)));
                asm("fma.rn.f32x2 %0, %1, %2, %0;" : "+l"(acc[0][2*f4])   : "l"(p20), "l"(v0));
                asm("fma.rn.f32x2 %0, %1, %2, %0;" : "+l"(acc[0][2*f4+1]) : "l"(p20), "l"(v1));
                asm("fma.rn.f32x2 %0, %1, %2, %0;" : "+l"(acc[1][2*f4])   : "l"(p21), "l"(v0));
                asm("fma.rn.f32x2 %0, %1, %2, %0;" : "+l"(acc[1][2*f4+1]) : "l"(p21), "l"(v1));
            }
        }
    }

    // ---- Epilogue: cross-lane reduce, divide, ELU ----
    float L0 = lsum0, L1 = lsum1;
#pragma unroll
    for (int o = 16; o; o >>= 1) {
        L0 += __shfl_xor_sync(0xffffffffu, L0, o);
        L1 += __shfl_xor_sync(0xffffffffu, L1, o);
    }
    __syncthreads();
    float* red = smem2 + w * (32 * 33);
#pragma unroll 1
    for (int r = 0; r < 2; ++r) {
#pragma unroll
        for (int j = 0; j < 16; ++j) {
            float lo, hi;
            asm("mov.b64 {%0, %1}, %2;" : "=f"(lo), "=f"(hi) : "l"(acc[r][j]));
            red[lane * 33 + 2 * j]     = lo;
            red[lane * 33 + 2 * j + 1] = hi;
        }
        __syncwarp();
        float tot = 0.f;
#pragma unroll 8
        for (int jj = 0; jj < 32; ++jj) tot += red[jj * 33 + lane];
        const float L = r ? L1 : L0;
        const int row = r ? row1 : row0;
        const float hv = tot / L;
        out[row * OUT_F + lane] = hv > 0.f ? hv : expm1f(hv);
        __syncwarp();
    }
}

// ---------------------------------------------------------------------------
extern "C" void kernel_launch(void* const* d_in, const int* in_sizes, int n_in,
                              void* d_out, int out_size)
{
    const float* h   = (const float*)d_in[0];
    const int*   adj = (const int*)  d_in[1];
    const float* W   = (const float*)d_in[2];
    const float* a   = (const float*)d_in[3];
    float*       out = (float*)d_out;

    gat_gemm_kernel<<<N_NODES / 4, 128>>>(h, W, a);

    cudaFuncSetAttribute(gat_attn_kernel,
                         cudaFuncAttributeMaxDynamicSharedMemorySize, SMEM_BYTES);
    gat_attn_kernel<<<GRID, THREADS, SMEM_BYTES>>>(adj, a, out);
}

// round 11
// speedup vs baseline: 1.1207x; 1.1207x over previous
#include <cuda_runtime.h>
#include <math.h>
#include <stdint.h>

#define N_NODES 2048
#define IN_F    128
#define OUT_F   32
#define KC      128
#define NTILES  (N_NODES / KC)          // 16
#define NSTEP   (KC / 32)               // 4
#define LOG2E   1.4426950408889634f
#define PBIAS   8.0f                    // P stored as 2^(e-8) fp16; cancels in num/L

// Score kernel: 128 CTAs x 256 thr (8 warps x 2 rows = 16 rows/CTA)
#define S_THREADS 256
#define S_STAGE_BYTES (KC * OUT_F * 2 + KC * 4)   // 8704
#define S_SMEM_BYTES  (2 * S_STAGE_BYTES)         // 17408

// Agg kernel: 128 CTAs x 256 thr (8 warps x 2 rows = 16 rows/CTA)
#define A_THREADS 256
#define A_STAGE_BYTES (KC * OUT_F * 4)            // 16384
#define A_SMEM_BYTES  33792                       // max(2*16384, 8*32*33*4)

__device__ float          g_Wh1[N_NODES * OUT_F];   // fp32 Wh1 (agg)
__device__ unsigned short g_Wh2h[N_NODES * OUT_F];  // fp16 Wh2 (score)
__device__ float          g_c6L[N_NODES];           // log2e*0.6*dot(a,Wh1[i]) - PBIAS
__device__ float          g_dk6L[N_NODES];          // log2e*0.6*dot(a,Wh2[k])
__device__ unsigned short g_P[N_NODES * N_NODES];   // fp16 p (biased)
__device__ float          g_L[N_NODES];             // row sums (biased, exact per row)

// ---------------------------------------------------------------------------
// Kernel 1: projections + constants (fp16 Wh2 copy). 512 CTAs x 128 thr.
// ---------------------------------------------------------------------------
__global__ __launch_bounds__(128) void gat_gemm_kernel(
    const float* __restrict__ h, const float* __restrict__ W,
    const float* __restrict__ a)
{
    __shared__ float Ws[2 * IN_F * OUT_F];
    __shared__ float hs[4][IN_F];
    const int tid = threadIdx.x, w = tid >> 5, lane = tid & 31;
    const int row0 = blockIdx.x * 4;
    {
        const uint32_t wsb = (uint32_t)__cvta_generic_to_shared(Ws);
        const uint32_t hsb = (uint32_t)__cvta_generic_to_shared(&hs[0][0]);
        const float4* gw = (const float4*)W;
        const float4* gh = (const float4*)(h + (size_t)row0 * IN_F);
#pragma unroll
        for (int i = 0; i < 16; ++i)
            asm volatile("cp.async.cg.shared.global [%0], [%1], 16;"
                         :: "r"(wsb + (uint32_t)((tid + i * 128) * 16)),
                            "l"(gw + tid + i * 128) : "memory");
        asm volatile("cp.async.cg.shared.global [%0], [%1], 16;"
                     :: "r"(hsb + (uint32_t)(tid * 16)), "l"(gh + tid) : "memory");
        asm volatile("cp.async.commit_group;" ::: "memory");
        asm volatile("cp.async.wait_group 0;" ::: "memory");
    }
    __syncthreads();

    const int row = row0 + w;
    float wh1 = 0.f, wh2 = 0.f;
#pragma unroll 8
    for (int j = 0; j < IN_F; ++j) {
        const float hv = hs[w][j];
        wh1 = fmaf(hv, Ws[j * OUT_F + lane], wh1);
        wh2 = fmaf(hv, Ws[(IN_F + j) * OUT_F + lane], wh2);
    }
    g_Wh1[row * OUT_F + lane] = wh1;
    unsigned short h2;
    asm("cvt.rn.f16.f32 %0, %1;" : "=h"(h2) : "f"(wh2));
    g_Wh2h[row * OUT_F + lane] = h2;

    const float av = __ldg(a + lane);
    float c = av * wh1, d = av * wh2;
#pragma unroll
    for (int o = 16; o; o >>= 1) {
        c += __shfl_xor_sync(0xffffffffu, c, o);
        d += __shfl_xor_sync(0xffffffffu, d, o);
    }
    if (lane == 0) {
        g_c6L[row]  = (0.6f * LOG2E) * c - PBIAS;
        g_dk6L[row] = (0.6f * LOG2E) * d;
    }
}

// ---------------------------------------------------------------------------
// Kernel 2: scores -> masked p (fp16, biased) + exact row sums.
// ---------------------------------------------------------------------------
extern __shared__ float smem2[];

__device__ __forceinline__ void issue_tile_score(int t, uint32_t smem_u, int tid)
{
    const uint32_t sb = smem_u + (t & 1) * S_STAGE_BYTES;
    const float4* g2 = (const float4*)(g_Wh2h + (size_t)t * (KC * OUT_F));
    for (int i = tid; i < KC * 4; i += S_THREADS) {      // 512 chunks, 2 iters
        int kk = i >> 2, q = i & 3;
        uint32_t soff = (uint32_t)(kk * 64 + ((q ^ ((kk >> 1) & 3)) << 4));
        asm volatile("cp.async.cg.shared.global [%0], [%1], 16;"
                     :: "r"(sb + soff), "l"(g2 + i) : "memory");
    }
    const float4* gd = (const float4*)(g_dk6L + t * KC);
    if (tid < KC / 4)
        asm volatile("cp.async.ca.shared.global [%0], [%1], 16;"
                     :: "r"(sb + (uint32_t)(KC * OUT_F * 2 + tid * 16)), "l"(gd + tid) : "memory");
    asm volatile("cp.async.commit_group;" ::: "memory");
}

__global__ __launch_bounds__(S_THREADS, 2) void gat_score_kernel(
    const int* __restrict__ adj, const float* __restrict__ a)
{
    const int tid = threadIdx.x, w = tid >> 5, lane = tid & 31;
    const uint32_t smem_u = (uint32_t)__cvta_generic_to_shared(smem2);
    const int row0 = blockIdx.x * 16 + 2 * w;   // 128 CTAs x 16 rows = 2048
    const int row1 = row0 + 1;

    uint32_t wh1pH[2][16], a4LH[16];
#pragma unroll
    for (int j = 0; j < 16; ++j) {
        float a0 = __ldg(a + 2 * j), a1 = __ldg(a + 2 * j + 1);
        float A0 = (0.4f * LOG2E) * a0, A1 = (0.4f * LOG2E) * a1;
        float x0 = g_Wh1[row0 * OUT_F + 2 * j], x1 = g_Wh1[row0 * OUT_F + 2 * j + 1];
        float y0 = g_Wh1[row1 * OUT_F + 2 * j], y1 = g_Wh1[row1 * OUT_F + 2 * j + 1];
        asm("{.reg .f16 l, hh; cvt.rn.f16.f32 l, %1; cvt.rn.f16.f32 hh, %2; mov.b32 %0, {l, hh};}"
            : "=r"(a4LH[j]) : "f"(A0), "f"(A1));
        asm("{.reg .f16 l, hh; cvt.rn.f16.f32 l, %1; cvt.rn.f16.f32 hh, %2; mov.b32 %0, {l, hh};}"
            : "=r"(wh1pH[0][j]) : "f"(x0), "f"(x1));
        asm("{.reg .f16 l, hh; cvt.rn.f16.f32 l, %1; cvt.rn.f16.f32 hh, %2; mov.b32 %0, {l, hh};}"
            : "=r"(wh1pH[1][j]) : "f"(y0), "f"(y1));
    }
    const float c0 = g_c6L[row0], c1 = g_c6L[row1];   // pre-biased
    float lsum0 = 0.f, lsum1 = 0.f;

    const int* adjr0 = adj + (size_t)row0 * N_NODES;
    const int* adjr1 = adj + (size_t)row1 * N_NODES;
    unsigned short* p0base = g_P + (size_t)row0 * N_NODES + lane;
    unsigned short* p1base = g_P + (size_t)row1 * N_NODES + lane;

    int am0[NSTEP], am1[NSTEP];
#pragma unroll
    for (int s = 0; s < NSTEP; ++s) {
        am0[s] = __ldg(adjr0 + (s << 5) + lane);
        am1[s] = __ldg(adjr1 + (s << 5) + lane);
    }

    issue_tile_score(0, smem_u, tid);

#pragma unroll 1
    for (int t = 0; t < NTILES; ++t) {
        __syncthreads();
        if (t + 1 < NTILES) {
            issue_tile_score(t + 1, smem_u, tid);
            asm volatile("cp.async.wait_group 1;" ::: "memory");
        } else {
            asm volatile("cp.async.wait_group 0;" ::: "memory");
        }
        __syncthreads();

        const uint32_t sb = smem_u + (t & 1) * S_STAGE_BYTES;
        const float* sdk = (const float*)((const char*)smem2
                           + (t & 1) * S_STAGE_BYTES + KC * OUT_F * 2);
        const int tn = (t + 1) & (NTILES - 1);
        const int* nadj0 = adjr0 + (tn << 7);
        const int* nadj1 = adjr1 + (tn << 7);

#pragma unroll
        for (int step = 0; step < NSTEP; ++step) {
            const int kk = (step << 5) | lane;
            const int av0 = am0[step], av1 = am1[step];
            am0[step] = __ldg(nadj0 + (step << 5) + lane);
            am1[step] = __ldg(nadj1 + (step << 5) + lane);
            const float dkv = sdk[kk];

            uint32_t hh[16];
            {
                const uint32_t rb = sb + (uint32_t)(kk * 64);
                const int sw = (kk >> 1) & 3;
#pragma unroll
                for (int q = 0; q < 4; ++q)
                    asm volatile("ld.shared.v4.b32 {%0, %1, %2, %3}, [%4];"
                                 : "=r"(hh[4*q]), "=r"(hh[4*q+1]), "=r"(hh[4*q+2]), "=r"(hh[4*q+3])
                                 : "r"(rb + (uint32_t)((q ^ sw) << 4)));
            }
            uint32_t s0[4] = {0,0,0,0}, s1[4] = {0,0,0,0};
#pragma unroll
            for (int j = 0; j < 16; ++j) {
                uint32_t t0, t1;
                asm("add.rn.f16x2 %0, %1, %2;" : "=r"(t0) : "r"(wh1pH[0][j]), "r"(hh[j]));
                t0 &= 0x7fff7fffu;
                asm("fma.rn.f16x2 %0, %1, %2, %0;" : "+r"(s0[j & 3]) : "r"(a4LH[j]), "r"(t0));
                asm("add.rn.f16x2 %0, %1, %2;" : "=r"(t1) : "r"(wh1pH[1][j]), "r"(hh[j]));
                t1 &= 0x7fff7fffu;
                asm("fma.rn.f16x2 %0, %1, %2, %0;" : "+r"(s1[j & 3]) : "r"(a4LH[j]), "r"(t1));
            }
            const int koff = (t << 7) + (step << 5);   // lane already in base
            {
                uint32_t u; float lo, hi, e, p, pu; unsigned short us;
                asm("add.rn.f16x2 %0, %1, %2;" : "=r"(u) : "r"(s0[0]), "r"(s0[1]));
                asm("add.rn.f16x2 %0, %1, %2;" : "=r"(s0[2]) : "r"(s0[2]), "r"(s0[3]));
                asm("add.rn.f16x2 %0, %1, %2;" : "=r"(u) : "r"(u), "r"(s0[2]));
                asm("{.reg .f16 l, hh; mov.b32 {l, hh}, %2; cvt.f32.f16 %0, l; cvt.f32.f16 %1, hh;}"
                    : "=f"(lo), "=f"(hi) : "r"(u));
                e = (c0 + dkv) + (lo + hi);
                asm("ex2.approx.f32 %0, %1;" : "=f"(p) : "f"(e));
                p = (av0 > 0) ? p : 0.f;
                asm("cvt.rn.f16.f32 %0, %1;" : "=h"(us) : "f"(p));
                asm("cvt.f32.f16 %0, %1;" : "=f"(pu) : "h"(us));
                lsum0 += pu;
                p0base[koff] = us;
                asm("add.rn.f16x2 %0, %1, %2;" : "=r"(u) : "r"(s1[0]), "r"(s1[1]));
                asm("add.rn.f16x2 %0, %1, %2;" : "=r"(s1[2]) : "r"(s1[2]), "r"(s1[3]));
                asm("add.rn.f16x2 %0, %1, %2;" : "=r"(u) : "r"(u), "r"(s1[2]));
                asm("{.reg .f16 l, hh; mov.b32 {l, hh}, %2; cvt.f32.f16 %0, l; cvt.f32.f16 %1, hh;}"
                    : "=f"(lo), "=f"(hi) : "r"(u));
                e = (c1 + dkv) + (lo + hi);
                asm("ex2.approx.f32 %0, %1;" : "=f"(p) : "f"(e));
                p = (av1 > 0) ? p : 0.f;
                asm("cvt.rn.f16.f32 %0, %1;" : "=h"(us) : "f"(p));
                asm("cvt.f32.f16 %0, %1;" : "=f"(pu) : "h"(us));
                lsum1 += pu;
                p1base[koff] = us;
            }
        }
    }

#pragma unroll
    for (int o = 16; o; o >>= 1) {
        lsum0 += __shfl_xor_sync(0xffffffffu, lsum0, o);
        lsum1 += __shfl_xor_sync(0xffffffffu, lsum1, o);
    }
    if (lane == 0) { g_L[row0] = lsum0; g_L[row1] = lsum1; }
}

// ---------------------------------------------------------------------------
// Kernel 3: out = ELU( (P @ Wh1) / L ).  2 rows/lane, epilogue finalizes.
// ---------------------------------------------------------------------------
__device__ __forceinline__ void issue_tile_agg(int t, uint32_t smem_u, int tid)
{
    const uint32_t w1b = smem_u + (t & 1) * A_STAGE_BYTES;
    const float4* g1 = ((const float4*)g_Wh1) + t * (KC * 8);
    for (int i = tid; i < KC * 8; i += A_THREADS) {      // 1024 chunks, 4 iters
        int kk = i >> 3, f4 = i & 7;
        uint32_t soff = (uint32_t)(((kk << 3) | (f4 ^ (kk & 7))) << 4);
        asm volatile("cp.async.cg.shared.global [%0], [%1], 16;"
                     :: "r"(w1b + soff), "l"(g1 + i) : "memory");
    }
    asm volatile("cp.async.commit_group;" ::: "memory");
}

__global__ __launch_bounds__(A_THREADS, 2) void gat_agg_kernel(float* __restrict__ out)
{
    const int tid = threadIdx.x, w = tid >> 5, lane = tid & 31;
    const uint32_t smem_u = (uint32_t)__cvta_generic_to_shared(smem2);
    const int row0 = blockIdx.x * 16 + 2 * w;
    const int row1 = row0 + 1;

    unsigned long long acc[2][16];
#pragma unroll
    for (int j = 0; j < 16; ++j) { acc[0][j] = 0ull; acc[1][j] = 0ull; }

    const unsigned short* pB0 = g_P + (size_t)row0 * N_NODES + lane;
    const unsigned short* pB1 = g_P + (size_t)row1 * N_NODES + lane;

    unsigned pr0[NSTEP], pr1[NSTEP];
#pragma unroll
    for (int s = 0; s < NSTEP; ++s) {
        pr0[s] = __ldg(pB0 + (s << 5));
        pr1[s] = __ldg(pB1 + (s << 5));
    }

    issue_tile_agg(0, smem_u, tid);

#pragma unroll 1
    for (int t = 0; t < NTILES; ++t) {
        __syncthreads();
        if (t + 1 < NTILES) {
            issue_tile_agg(t + 1, smem_u, tid);
            asm volatile("cp.async.wait_group 1;" ::: "memory");
        } else {
            asm volatile("cp.async.wait_group 0;" ::: "memory");
        }
        __syncthreads();

        const uint32_t w1b = smem_u + (t & 1) * A_STAGE_BYTES;
        const int noff = ((t + 1) & (NTILES - 1)) << 7;

#pragma unroll
        for (int step = 0; step < NSTEP; ++step) {
            const int kk = (step << 5) | lane;
            float pf0, pf1;
            asm("cvt.f32.f16 %0, %1;" : "=f"(pf0) : "h"((unsigned short)pr0[step]));
            asm("cvt.f32.f16 %0, %1;" : "=f"(pf1) : "h"((unsigned short)pr1[step]));
            pr0[step] = __ldg(pB0 + noff + (step << 5));
            pr1[step] = __ldg(pB1 + noff + (step << 5));
            unsigned long long p20, p21;
            asm("mov.b64 %0, {%1, %1};" : "=l"(p20) : "f"(pf0));
            asm("mov.b64 %0, {%1, %1};" : "=l"(p21) : "f"(pf1));
            const uint32_t rb1 = w1b + (uint32_t)(kk << 7);
            const int sx = kk & 7;
#pragma unroll
            for (int f4 = 0; f4 < 8; ++f4) {
                unsigned long long v0, v1;
                asm volatile("ld.shared.v2.b64 {%0, %1}, [%2];"
                             : "=l"(v0), "=l"(v1) : "r"(rb1 + (uint32_t)((f4 ^ sx) << 4)));
                asm("fma.rn.f32x2 %0, %1, %2, %0;" : "+l"(acc[0][2*f4])   : "l"(p20), "l"(v0));
                asm("fma.rn.f32x2 %0, %1, %2, %0;" : "+l"(acc[0][2*f4+1]) : "l"(p20), "l"(v1));
                asm("fma.rn.f32x2 %0, %1, %2, %0;" : "+l"(acc[1][2*f4])   : "l"(p21), "l"(v0));
                asm("fma.rn.f32x2 %0, %1, %2, %0;" : "+l"(acc[1][2*f4+1]) : "l"(p21), "l"(v1));
            }
        }
    }

    // Epilogue: per-warp transpose reduce, divide by L, ELU
    __syncthreads();
    float* red = smem2 + w * (32 * 33);
#pragma unroll 1
    for (int r = 0; r < 2; ++r) {
#pragma unroll
        for (int j = 0; j < 16; ++j) {
            float lo, hi;
            asm("mov.b64 {%0, %1}, %2;" : "=f"(lo), "=f"(hi) : "l"(acc[r][j]));
            red[lane * 33 + 2 * j]     = lo;
            red[lane * 33 + 2 * j + 1] = hi;
        }
        __syncwarp();
        float tot = 0.f;
#pragma unroll 8
        for (int jj = 0; jj < 32; ++jj) tot += red[jj * 33 + lane];
        const int row = r ? row1 : row0;
        const float hv = tot / __ldg(g_L + row);
        out[row * OUT_F + lane] = hv > 0.f ? hv : expm1f(hv);
        __syncwarp();
    }
}

// ---------------------------------------------------------------------------
extern "C" void kernel_launch(void* const* d_in, const int* in_sizes, int n_in,
                              void* d_out, int out_size)
{
    const float* h   = (const float*)d_in[0];
    const int*   adj = (const int*)  d_in[1];
    const float* W   = (const float*)d_in[2];
    const float* a   = (const float*)d_in[3];
    float*       out = (float*)d_out;

    gat_gemm_kernel<<<N_NODES / 4, 128>>>(h, W, a);
    gat_score_kernel<<<128, S_THREADS, S_SMEM_BYTES>>>(adj, a);
    gat_agg_kernel<<<128, A_THREADS, A_SMEM_BYTES>>>(out);
}

// round 12
// speedup vs baseline: 1.4642x; 1.3064x over previous
#include <cuda_runtime.h>
#include <math.h>
#include <stdint.h>

#define N_NODES 2048
#define IN_F    128
#define OUT_F   32
#define KC      128
#define NTILES  (N_NODES / KC)          // 16
#define NSTEP   (KC / 32)               // 4
#define WARPS   7
#define THREADS (WARPS * 32)            // 224
#define GRID    148                     // 148*14 = 2072 >= 2048 rows, 1 CTA/SM
#define LOG2E 1.4426950408889634f

// Stage layout: [0,8K) fp16 score tile | [8K,24K) fp32 agg tile | [24K,+512) dk
#define SC_BYTES    (KC * OUT_F * 2)          // 8192
#define AG_BYTES    (KC * OUT_F * 4)          // 16384
#define DK_OFF      (SC_BYTES + AG_BYTES)     // 24576
#define STAGE_BYTES (DK_OFF + KC * 4)         // 25088
#define SMEM_BYTES  (2 * STAGE_BYTES)         // 50176

__device__ float          g_Wh1[N_NODES * OUT_F];   // fp32 Wh1 (agg tile)
__device__ unsigned short g_Wh2h[N_NODES * OUT_F];  // fp16 Wh2 (score tile)
__device__ float          g_c6L[N_NODES];           // log2e*0.6*dot(a,Wh1[i])
__device__ float          g_dk6L[N_NODES];          // log2e*0.6*dot(a,Wh2[k])

// ---------------------------------------------------------------------------
// Kernel 1: projections + constants (fp16 Wh2 copy). 512 CTAs x 128 thr.
// ---------------------------------------------------------------------------
__global__ __launch_bounds__(128) void gat_gemm_kernel(
    const float* __restrict__ h, const float* __restrict__ W,
    const float* __restrict__ a)
{
    __shared__ float Ws[2 * IN_F * OUT_F];
    __shared__ float hs[4][IN_F];
    const int tid = threadIdx.x, w = tid >> 5, lane = tid & 31;
    const int row0 = blockIdx.x * 4;
    {
        const uint32_t wsb = (uint32_t)__cvta_generic_to_shared(Ws);
        const uint32_t hsb = (uint32_t)__cvta_generic_to_shared(&hs[0][0]);
        const float4* gw = (const float4*)W;
        const float4* gh = (const float4*)(h + (size_t)row0 * IN_F);
#pragma unroll
        for (int i = 0; i < 16; ++i)
            asm volatile("cp.async.cg.shared.global [%0], [%1], 16;"
                         :: "r"(wsb + (uint32_t)((tid + i * 128) * 16)),
                            "l"(gw + tid + i * 128) : "memory");
        asm volatile("cp.async.cg.shared.global [%0], [%1], 16;"
                     :: "r"(hsb + (uint32_t)(tid * 16)), "l"(gh + tid) : "memory");
        asm volatile("cp.async.commit_group;" ::: "memory");
        asm volatile("cp.async.wait_group 0;" ::: "memory");
    }
    __syncthreads();

    const int row = row0 + w;
    float wh1 = 0.f, wh2 = 0.f;
#pragma unroll 8
    for (int j = 0; j < IN_F; ++j) {
        const float hv = hs[w][j];
        wh1 = fmaf(hv, Ws[j * OUT_F + lane], wh1);
        wh2 = fmaf(hv, Ws[(IN_F + j) * OUT_F + lane], wh2);
    }
    g_Wh1[row * OUT_F + lane] = wh1;
    unsigned short h2;
    asm("cvt.rn.f16.f32 %0, %1;" : "=h"(h2) : "f"(wh2));
    g_Wh2h[row * OUT_F + lane] = h2;

    const float av = __ldg(a + lane);
    float c = av * wh1, d = av * wh2;
#pragma unroll
    for (int o = 16; o; o >>= 1) {
        c += __shfl_xor_sync(0xffffffffu, c, o);
        d += __shfl_xor_sync(0xffffffffu, d, o);
    }
    if (lane == 0) {
        g_c6L[row]  = (0.6f * LOG2E) * c;
        g_dk6L[row] = (0.6f * LOG2E) * d;
    }
}

// ---------------------------------------------------------------------------
// Kernel 2: fused score(fp16x2) + softmax + agg(fp32x2) + ELU.
// 224 thr x 148 CTAs (R9 shape), fp16 score path (R10 math).
// ---------------------------------------------------------------------------
extern __shared__ float smem2[];

__device__ __forceinline__ void issue_tile(int t, uint32_t smem_u, int tid)
{
    const uint32_t sb = smem_u + (t & 1) * STAGE_BYTES;
    // fp16 score tile: KC rows x 64B, swizzle q^((kk>>1)&3)
    const float4* g2 = (const float4*)(g_Wh2h + (size_t)t * (KC * OUT_F));
    for (int i = tid; i < KC * 4; i += THREADS) {
        int kk = i >> 2, q = i & 3;
        uint32_t soff = (uint32_t)(kk * 64 + ((q ^ ((kk >> 1) & 3)) << 4));
        asm volatile("cp.async.cg.shared.global [%0], [%1], 16;"
                     :: "r"(sb + soff), "l"(g2 + i) : "memory");
    }
    // fp32 agg tile: KC rows x 128B, swizzle f4^(kk&7)
    const float4* g1 = ((const float4*)g_Wh1) + t * (KC * 8);
    for (int i = tid; i < KC * 8; i += THREADS) {
        int kk = i >> 3, f4 = i & 7;
        uint32_t soff = (uint32_t)(((kk << 3) | (f4 ^ (kk & 7))) << 4);
        asm volatile("cp.async.cg.shared.global [%0], [%1], 16;"
                     :: "r"(sb + SC_BYTES + soff), "l"(g1 + i) : "memory");
    }
    const float* gd = g_dk6L + t * KC;
    for (int i = tid; i < KC; i += THREADS)
        asm volatile("cp.async.ca.shared.global [%0], [%1], 4;"
                     :: "r"(sb + DK_OFF + (uint32_t)(i * 4)), "l"(gd + i) : "memory");
    asm volatile("cp.async.commit_group;" ::: "memory");
}

__global__ __launch_bounds__(THREADS, 1) void gat_attn_kernel(
    const int* __restrict__ adj, const float* __restrict__ a,
    float* __restrict__ out)
{
    const int tid = threadIdx.x, w = tid >> 5, lane = tid & 31;
    const uint32_t smem_u = (uint32_t)__cvta_generic_to_shared(smem2);
    int row0 = blockIdx.x * 14 + 2 * w;
    int row1 = row0 + 1;
    if (row1 >= N_NODES) { row0 = N_NODES - 2; row1 = N_NODES - 1; }

    // fp16x2 score operands; fp32x2 accumulators
    uint32_t wh1pH[2][16], a4LH[16];
    unsigned long long acc[2][16];
#pragma unroll
    for (int j = 0; j < 16; ++j) {
        float a0 = __ldg(a + 2 * j), a1 = __ldg(a + 2 * j + 1);
        float A0 = (0.4f * LOG2E) * a0, A1 = (0.4f * LOG2E) * a1;
        float x0 = g_Wh1[row0 * OUT_F + 2 * j], x1 = g_Wh1[row0 * OUT_F + 2 * j + 1];
        float y0 = g_Wh1[row1 * OUT_F + 2 * j], y1 = g_Wh1[row1 * OUT_F + 2 * j + 1];
        asm("{.reg .f16 l, hh; cvt.rn.f16.f32 l, %1; cvt.rn.f16.f32 hh, %2; mov.b32 %0, {l, hh};}"
            : "=r"(a4LH[j]) : "f"(A0), "f"(A1));
        asm("{.reg .f16 l, hh; cvt.rn.f16.f32 l, %1; cvt.rn.f16.f32 hh, %2; mov.b32 %0, {l, hh};}"
            : "=r"(wh1pH[0][j]) : "f"(x0), "f"(x1));
        asm("{.reg .f16 l, hh; cvt.rn.f16.f32 l, %1; cvt.rn.f16.f32 hh, %2; mov.b32 %0, {l, hh};}"
            : "=r"(wh1pH[1][j]) : "f"(y0), "f"(y1));
        acc[0][j] = 0ull; acc[1][j] = 0ull;
    }
    const float c0 = g_c6L[row0], c1 = g_c6L[row1];
    float lsum0 = 0.f, lsum1 = 0.f;

    const int* adjr0 = adj + (size_t)row0 * N_NODES;
    const int* adjr1 = adj + (size_t)row1 * N_NODES;
    int am0[NSTEP], am1[NSTEP];
#pragma unroll
    for (int s = 0; s < NSTEP; ++s) {
        am0[s] = __ldg(adjr0 + (s << 5) + lane);
        am1[s] = __ldg(adjr1 + (s << 5) + lane);
    }

    issue_tile(0, smem_u, tid);

#pragma unroll 1
    for (int t = 0; t < NTILES; ++t) {
        __syncthreads();
        if (t + 1 < NTILES) {
            issue_tile(t + 1, smem_u, tid);
            asm volatile("cp.async.wait_group 1;" ::: "memory");
        } else {
            asm volatile("cp.async.wait_group 0;" ::: "memory");
        }
        __syncthreads();

        const uint32_t sb = smem_u + (t & 1) * STAGE_BYTES;
        const float* sdk = (const float*)((const char*)smem2 + (t & 1) * STAGE_BYTES + DK_OFF);
        const int tn = (t + 1) & (NTILES - 1);
        const int* nadj0 = adjr0 + (tn << 7);
        const int* nadj1 = adjr1 + (tn << 7);

#pragma unroll
        for (int step = 0; step < NSTEP; ++step) {
            const int kk = (step << 5) | lane;
            const int av0 = am0[step], av1 = am1[step];
            am0[step] = __ldg(nadj0 + (step << 5) + lane);
            am1[step] = __ldg(nadj1 + (step << 5) + lane);
            const float dkv = sdk[kk];

            // ---- Score (fp16x2): 4 swizzled LDS.128 -> 16 fp16x2 ----
            uint32_t hh[16];
            {
                const uint32_t rb = sb + (uint32_t)(kk * 64);
                const int sw = (kk >> 1) & 3;
#pragma unroll
                for (int q = 0; q < 4; ++q)
                    asm volatile("ld.shared.v4.b32 {%0, %1, %2, %3}, [%4];"
                                 : "=r"(hh[4*q]), "=r"(hh[4*q+1]), "=r"(hh[4*q+2]), "=r"(hh[4*q+3])
                                 : "r"(rb + (uint32_t)((q ^ sw) << 4)));
            }
            uint32_t s0[4] = {0,0,0,0}, s1[4] = {0,0,0,0};
#pragma unroll
            for (int j = 0; j < 16; ++j) {
                uint32_t t0, t1;
                asm("add.rn.f16x2 %0, %1, %2;" : "=r"(t0) : "r"(wh1pH[0][j]), "r"(hh[j]));
                t0 &= 0x7fff7fffu;
                asm("fma.rn.f16x2 %0, %1, %2, %0;" : "+r"(s0[j & 3]) : "r"(a4LH[j]), "r"(t0));
                asm("add.rn.f16x2 %0, %1, %2;" : "=r"(t1) : "r"(wh1pH[1][j]), "r"(hh[j]));
                t1 &= 0x7fff7fffu;
                asm("fma.rn.f16x2 %0, %1, %2, %0;" : "+r"(s1[j & 3]) : "r"(a4LH[j]), "r"(t1));
            }
            float p0, p1;
            {
                uint32_t u; float lo, hi, e;
                asm("add.rn.f16x2 %0, %1, %2;" : "=r"(u) : "r"(s0[0]), "r"(s0[1]));
                asm("add.rn.f16x2 %0, %1, %2;" : "=r"(s0[2]) : "r"(s0[2]), "r"(s0[3]));
                asm("add.rn.f16x2 %0, %1, %2;" : "=r"(u) : "r"(u), "r"(s0[2]));
                asm("{.reg .f16 l, hh; mov.b32 {l, hh}, %2; cvt.f32.f16 %0, l; cvt.f32.f16 %1, hh;}"
                    : "=f"(lo), "=f"(hi) : "r"(u));
                e = (c0 + dkv) + (lo + hi);
                asm("ex2.approx.f32 %0, %1;" : "=f"(p0) : "f"(e));
                p0 = (av0 > 0) ? p0 : 0.f;
                asm("add.rn.f16x2 %0, %1, %2;" : "=r"(u) : "r"(s1[0]), "r"(s1[1]));
                asm("add.rn.f16x2 %0, %1, %2;" : "=r"(s1[2]) : "r"(s1[2]), "r"(s1[3]));
                asm("add.rn.f16x2 %0, %1, %2;" : "=r"(u) : "r"(u), "r"(s1[2]));
                asm("{.reg .f16 l, hh; mov.b32 {l, hh}, %2; cvt.f32.f16 %0, l; cvt.f32.f16 %1, hh;}"
                    : "=f"(lo), "=f"(hi) : "r"(u));
                e = (c1 + dkv) + (lo + hi);
                asm("ex2.approx.f32 %0, %1;" : "=f"(p1) : "f"(e));
                p1 = (av1 > 0) ? p1 : 0.f;
            }
            lsum0 += p0; lsum1 += p1;
            unsigned long long p20, p21;
            asm("mov.b64 %0, {%1, %1};" : "=l"(p20) : "f"(p0));
            asm("mov.b64 %0, {%1, %1};" : "=l"(p21) : "f"(p1));

            // ---- Aggregate (fp32x2): 8 swizzled LDS.128 ----
            const uint32_t rb1 = sb + SC_BYTES + (uint32_t)(kk << 7);
            const int sx = kk & 7;
#pragma unroll
            for (int f4 = 0; f4 < 8; ++f4) {
                unsigned long long v0, v1;
                asm volatile("ld.shared.v2.b64 {%0, %1}, [%2];"
                             : "=l"(v0), "=l"(v1) : "r"(rb1 + (uint32_t)((f4 ^ sx) << 4)));
                asm("fma.rn.f32x2 %0, %1, %2, %0;" : "+l"(acc[0][2*f4])   : "l"(p20), "l"(v0));
                asm("fma.rn.f32x2 %0, %1, %2, %0;" : "+l"(acc[0][2*f4+1]) : "l"(p20), "l"(v1));
                asm("fma.rn.f32x2 %0, %1, %2, %0;" : "+l"(acc[1][2*f4])   : "l"(p21), "l"(v0));
                asm("fma.rn.f32x2 %0, %1, %2, %0;" : "+l"(acc[1][2*f4+1]) : "l"(p21), "l"(v1));
            }
        }
    }

    // ---- Epilogue: cross-lane reduce, divide, ELU ----
    float L0 = lsum0, L1 = lsum1;
#pragma unroll
    for (int o = 16; o; o >>= 1) {
        L0 += __shfl_xor_sync(0xffffffffu, L0, o);
        L1 += __shfl_xor_sync(0xffffffffu, L1, o);
    }
    __syncthreads();
    float* red = smem2 + w * (32 * 33);
#pragma unroll 1
    for (int r = 0; r < 2; ++r) {
#pragma unroll
        for (int j = 0; j < 16; ++j) {
            float lo, hi;
            asm("mov.b64 {%0, %1}, %2;" : "=f"(lo), "=f"(hi) : "l"(acc[r][j]));
            red[lane * 33 + 2 * j]     = lo;
            red[lane * 33 + 2 * j + 1] = hi;
        }
        __syncwarp();
        float tot = 0.f;
#pragma unroll 8
        for (int jj = 0; jj < 32; ++jj) tot += red[jj * 33 + lane];
        const float L = r ? L1 : L0;
        const int row = r ? row1 : row0;
        const float hv = tot / L;
        out[row * OUT_F + lane] = hv > 0.f ? hv : expm1f(hv);
        __syncwarp();
    }
}

// ---------------------------------------------------------------------------
extern "C" void kernel_launch(void* const* d_in, const int* in_sizes, int n_in,
                              void* d_out, int out_size)
{
    const float* h   = (const float*)d_in[0];
    const int*   adj = (const int*)  d_in[1];
    const float* W   = (const float*)d_in[2];
    const float* a   = (const float*)d_in[3];
    float*       out = (float*)d_out;

    gat_gemm_kernel<<<N_NODES / 4, 128>>>(h, W, a);

    cudaFuncSetAttribute(gat_attn_kernel,
                         cudaFuncAttributeMaxDynamicSharedMemorySize, SMEM_BYTES);
    gat_attn_kernel<<<GRID, THREADS, SMEM_BYTES>>>(adj, a, out);
}